// round 17
// baseline (speedup 1.0000x reference)
#include <cuda_runtime.h>
#include <math.h>

#define B_SZ   1024
#define HID    384
#define MH     300
#define OPAD   320   // padded row stride; cols 300..319 stay zero (zero-init globals)
#define NJT    16

typedef unsigned long long u64;

// Scratch (device globals; allocations forbidden). Zero-initialized at load;
// padding columns are never written, so they remain exactly 0.0f.
__device__ float g_s1[B_SZ * HID];
__device__ float g_s2[B_SZ * HID];
__device__ float g_Axb[B_SZ * OPAD];
__device__ float g_By [B_SZ * OPAD];
__device__ float g_klpart[B_SZ];
__device__ float g_T0[B_SZ];
__device__ float g_rowpart[NJT * B_SZ];   // [jt][i]
__device__ unsigned g_rowdone[16];        // k3 tiles done per i-group (target 16)
__device__ unsigned g_fin;
__device__ double g_accKL, g_accT0, g_accL;

__device__ __forceinline__ float softplusf(float x) {
    return fmaxf(x, 0.f) + log1pf(expf(-fabsf(x)));
}

// Packed f32x2 ops on u64-resident data
__device__ __forceinline__ u64 f2add_u(u64 a, u64 b) {
    u64 d; asm("add.rn.f32x2 %0, %1, %2;" : "=l"(d) : "l"(a), "l"(b)); return d;
}
__device__ __forceinline__ u64 f2fma_u(u64 a, u64 b, u64 c) {
    u64 d; asm("fma.rn.f32x2 %0, %1, %2, %3;" : "=l"(d) : "l"(a), "l"(b), "l"(c)); return d;
}
__device__ __forceinline__ u64 f2relu_u(u64 a) {
    float lo, hi;
    asm("mov.b64 {%0,%1}, %2;" : "=f"(lo), "=f"(hi) : "l"(a));
    lo = fmaxf(lo, 0.f);
    hi = fmaxf(hi, 0.f);
    u64 d;
    asm("mov.b64 %0, {%1,%2};" : "=l"(d) : "f"(lo), "f"(hi));
    return d;
}
__device__ __forceinline__ float f2hsum(u64 a) {
    float lo, hi;
    asm("mov.b64 {%0,%1}, %2;" : "=f"(lo), "=f"(hi) : "l"(a));
    return lo + hi;
}
__device__ __forceinline__ u64 fpack(float x, float y) {
    u64 d; asm("mov.b64 %0, {%1,%2};" : "=l"(d) : "f"(x), "f"(y)); return d;
}

// ---------------------------------------------------------------------------
// reset: clears control state at graph start (replay-safe)
// ---------------------------------------------------------------------------
__global__ void k_reset()
{
    g_fin = 0u;
    #pragma unroll
    for (int i = 0; i < 16; ++i) g_rowdone[i] = 0u;
    g_accKL = 0.0; g_accT0 = 0.0; g_accL = 0.0;
}

// ---------------------------------------------------------------------------
// K1 quarter: rows [base, base+256). grid 256, block 192. HBM-bound.
// ---------------------------------------------------------------------------
__global__ __launch_bounds__(192) void k1_fuse(
    const float* __restrict__ zl, const float* __restrict__ zv,
    const float* __restrict__ wl_g, const float* __restrict__ bl_g,
    const float* __restrict__ wv_g, const float* __restrict__ bv_g,
    const float* __restrict__ eps1, const float* __restrict__ eps2,
    int base)
{
    __shared__ float z1s[768], z2s[768];
    __shared__ float wls[20], wvs[36];
    __shared__ float redw[6];
    const int b = base + blockIdx.x, t = threadIdx.x;
    if (t < 20) wls[t] = wl_g[t];
    if (t >= 32 && t < 68) wvs[t - 32] = wv_g[t - 32];
    __syncthreads();
    const float bl = bl_g[0], bv = bv_g[0];
    {
        const float4* p = (const float4*)(zl + (size_t)b * 20 * 768) + t;
        float4 a = make_float4(bl, bl, bl, bl);
        #pragma unroll
        for (int s = 0; s < 20; ++s) {
            float4 v = p[s * 192];
            float w = wls[s];
            a.x = fmaf(v.x, w, a.x); a.y = fmaf(v.y, w, a.y);
            a.z = fmaf(v.z, w, a.z); a.w = fmaf(v.w, w, a.w);
        }
        ((float4*)z1s)[t] = a;
    }
    {
        const float4* p = (const float4*)(zv + (size_t)b * 36 * 768) + t;
        float4 a = make_float4(bv, bv, bv, bv);
        #pragma unroll
        for (int s = 0; s < 36; ++s) {
            float4 v = p[s * 192];
            float w = wvs[s];
            a.x = fmaf(v.x, w, a.x); a.y = fmaf(v.y, w, a.y);
            a.z = fmaf(v.z, w, a.z); a.w = fmaf(v.w, w, a.w);
        }
        ((float4*)z2s)[t] = a;
    }
    __syncthreads();
    float klacc = 0.f;
    #pragma unroll
    for (int q = 0; q < 2; ++q) {
        int k = t + q * 192;
        float mu1 = z1s[k], mu2 = z2s[k];
        float sg1 = softplusf(z1s[k + HID]) + 1e-7f;
        float sg2 = softplusf(z2s[k + HID]) + 1e-7f;
        float e1 = eps1[b * HID + k], e2 = eps2[b * HID + k];
        float s1v = fmaf(sg1, e1, mu1);
        float s2v = fmaf(sg2, e2, mu2);
        g_s1[b * HID + k] = s1v;
        g_s2[b * HID + k] = s2v;
        float d1 = (s1v - mu2) / sg2;
        float d2 = (s2v - mu1) / sg1;
        klacc += 0.5f * (d1 * d1 + d2 * d2 - e1 * e1 - e2 * e2);
    }
    #pragma unroll
    for (int off = 16; off > 0; off >>= 1)
        klacc += __shfl_xor_sync(0xFFFFFFFFu, klacc, off);
    if ((t & 31) == 0) redw[t >> 5] = klacc;
    __syncthreads();
    if (t == 0)
        g_klpart[b] = redw[0] + redw[1] + redw[2] + redw[3] + redw[4] + redw[5];
}

// ---------------------------------------------------------------------------
// K2 quarter: row-groups [4q, 4q+4). grid (4,5,2), block 256.
// ---------------------------------------------------------------------------
__global__ __launch_bounds__(256) void k2_gemm(
    const float* __restrict__ W1, const float* __restrict__ b1, int q)
{
    __shared__ u64 As[64][17];
    __shared__ u64 Ws[64][17];

    const int z  = blockIdx.z;
    const int r0 = (q * 4 + blockIdx.x) * 64;
    const int c0 = blockIdx.y * 64;
    const float* S = z ? g_s2 : g_s1;
    float*       O = z ? g_By : g_Axb;
    const int koff = z ? HID : 0;

    const int t  = threadIdx.x;
    const int tj = t & 15;
    const int ti = t >> 4;

    u64 acc[4][4];
    #pragma unroll
    for (int r = 0; r < 4; ++r)
        #pragma unroll
        for (int c = 0; c < 4; ++c) acc[r][c] = 0ull;

    for (int kk2 = 0; kk2 < 192; kk2 += 16) {
        __syncthreads();
        #pragma unroll
        for (int i = 0; i < 4; ++i) {
            int e = t + i * 256;
            int row = e >> 4, k2 = e & 15;
            As[row][k2] = *(const u64*)&S[(r0 + row) * HID + (kk2 + k2) * 2];
            int col = c0 + row;
            Ws[row][k2] = (col < MH)
                ? *(const u64*)&W1[col * 768 + koff + (kk2 + k2) * 2] : 0ull;
        }
        __syncthreads();
        #pragma unroll 4
        for (int k2 = 0; k2 < 16; ++k2) {
            u64 a[4], w[4];
            #pragma unroll
            for (int r = 0; r < 4; ++r) a[r] = As[ti + 16 * r][k2];
            #pragma unroll
            for (int c = 0; c < 4; ++c) w[c] = Ws[tj + 16 * c][k2];
            #pragma unroll
            for (int r = 0; r < 4; ++r)
                #pragma unroll
                for (int c = 0; c < 4; ++c)
                    acc[r][c] = f2fma_u(a[r], w[c], acc[r][c]);
        }
    }
    #pragma unroll
    for (int r = 0; r < 4; ++r) {
        int row = r0 + ti + 16 * r;
        #pragma unroll
        for (int c = 0; c < 4; ++c) {
            int col = c0 + tj + 16 * c;
            if (col < MH) {
                float v = f2hsum(acc[r][c]);
                if (z == 0) v += b1[col];
                O[row * OPAD + col] = v;
            }
        }
    }
}

// ---------------------------------------------------------------------------
// K3 shell q: tiles with max(it,jt)/4 == q.  grid 32q+16, block 256.
// Same tile body as R13 (64x64, u64-packed, prefetch pipeline, diagonal T0,
// per-it-group finisher with distributed double atomics).
// ---------------------------------------------------------------------------
__global__ __launch_bounds__(256) void k3_shell(
    const float* __restrict__ W2, const float* __restrict__ b2g,
    float* __restrict__ out, int q)
{
    __shared__ u64 Bys[64][17];
    __shared__ u64 Axs[64][17];
    __shared__ u64 w2s[160];
    __shared__ float rowred[64][17];
    __shared__ int sLast;
    __shared__ double sred[3][2];

    // shell -> (it, jt)
    int it, jt;
    {
        const int n = blockIdx.x;
        const int w = 4 * q + 4;
        if (n < 4 * w) { it = 4 * q + n / w; jt = n % w; }
        else { const int m = n - 4 * w; jt = 4 * q + m / (4 * q); it = m % (4 * q); }
    }
    const int i0 = it * 64, j0 = jt * 64;
    const int t  = threadIdx.x;
    const int tj = t & 15;
    const int ti = t >> 4;

    if (t < 160) {
        int k = 2 * t;
        float2 w = make_float2(k < MH ? W2[k] : 0.f,
                               k + 1 < MH ? W2[k + 1] : 0.f);
        w2s[t] = *(const u64*)&w;
    }

    const int rA = t >> 3,          fA = t & 7;
    const int rB = (t + 256) >> 3,  fB = t & 7;
    const float* byA = &g_By [(i0 + rA) * OPAD + fA * 4];
    const float* byB = &g_By [(i0 + rB) * OPAD + fB * 4];
    const float* axA = &g_Axb[(j0 + rA) * OPAD + fA * 4];
    const float* axB = &g_Axb[(j0 + rB) * OPAD + fB * 4];

    u64 acc[4][4];
    #pragma unroll
    for (int r = 0; r < 4; ++r)
        #pragma unroll
        for (int c = 0; c < 4; ++c) acc[r][c] = 0ull;

    float4 pb0 = *(const float4*)(byA);
    float4 pb1 = *(const float4*)(byB);
    float4 pa0 = *(const float4*)(axA);
    float4 pa1 = *(const float4*)(axB);

    for (int c = 0; c < 10; ++c) {
        __syncthreads();
        Bys[rA][2 * fA]     = fpack(pb0.x, pb0.y);
        Bys[rA][2 * fA + 1] = fpack(pb0.z, pb0.w);
        Bys[rB][2 * fB]     = fpack(pb1.x, pb1.y);
        Bys[rB][2 * fB + 1] = fpack(pb1.z, pb1.w);
        Axs[rA][2 * fA]     = fpack(pa0.x, pa0.y);
        Axs[rA][2 * fA + 1] = fpack(pa0.z, pa0.w);
        Axs[rB][2 * fB]     = fpack(pa1.x, pa1.y);
        Axs[rB][2 * fB + 1] = fpack(pa1.z, pa1.w);
        __syncthreads();
        if (c < 9) {
            int off = (c + 1) * 32;
            pb0 = *(const float4*)(byA + off);
            pb1 = *(const float4*)(byB + off);
            pa0 = *(const float4*)(axA + off);
            pa1 = *(const float4*)(axB + off);
        }
        #pragma unroll 4
        for (int k2 = 0; k2 < 16; ++k2) {
            u64 wp = w2s[c * 16 + k2];
            u64 a[4], b[4];
            #pragma unroll
            for (int cc = 0; cc < 4; ++cc) a[cc] = Axs[tj + 16 * cc][k2];
            #pragma unroll
            for (int r = 0; r < 4; ++r) b[r] = Bys[ti + 16 * r][k2];
            #pragma unroll
            for (int r = 0; r < 4; ++r)
                #pragma unroll
                for (int cc = 0; cc < 4; ++cc)
                    acc[r][cc] = f2fma_u(f2relu_u(f2add_u(a[cc], b[r])), wp,
                                         acc[r][cc]);
        }
    }

    const float b2v = b2g[0];

    if (jt == it && tj == ti) {
        #pragma unroll
        for (int r = 0; r < 4; ++r)
            g_T0[i0 + ti + 16 * r] = softplusf(f2hsum(acc[r][r]) + b2v);
    }

    __syncthreads();
    #pragma unroll
    for (int r = 0; r < 4; ++r) {
        float e = 0.f;
        #pragma unroll
        for (int cc = 0; cc < 4; ++cc)
            e += expf(f2hsum(acc[r][cc]) + b2v);
        rowred[ti + 16 * r][tj] = e;
    }
    __syncthreads();
    if (t < 64) {
        float s = 0.f;
        #pragma unroll
        for (int cc = 0; cc < 16; ++cc) s += rowred[t][cc];
        g_rowpart[jt * B_SZ + i0 + t] = s;
    }

    // ---- per-it-group finisher (16th arriving tile) ----
    __threadfence();
    __syncthreads();
    if (t == 0) {
        unsigned old = atomicAdd(&g_rowdone[it], 1u);
        sLast = (old == 15u);
    }
    __syncthreads();
    if (!sLast) return;
    __threadfence();   // acquire: all tiles' rowpart/T0 writes visible

    double kl = 0.0, t0 = 0.0, L = 0.0;
    if (t < 64) {
        int i = i0 + t;
        float rs = 0.f;
        #pragma unroll
        for (int j = 0; j < NJT; ++j)
            rs += g_rowpart[j * B_SZ + i];
        kl = (double)g_klpart[i];
        t0 = (double)g_T0[i];
        // logsumexp_j softplus(u) = log(B + sum_j e^u)
        L  = (double)logf((float)B_SZ + rs);
    }
    if (t < 64) {
        #pragma unroll
        for (int off = 16; off > 0; off >>= 1) {
            kl += __shfl_xor_sync(0xFFFFFFFFu, kl, off);
            t0 += __shfl_xor_sync(0xFFFFFFFFu, t0, off);
            L  += __shfl_xor_sync(0xFFFFFFFFu, L,  off);
        }
        if ((t & 31) == 0) {
            sred[0][t >> 5] = kl; sred[1][t >> 5] = t0; sred[2][t >> 5] = L;
        }
    }
    __syncthreads();
    if (t == 0) {
        atomicAdd(&g_accKL, sred[0][0] + sred[0][1]);
        atomicAdd(&g_accT0, sred[1][0] + sred[1][1]);
        atomicAdd(&g_accL,  sred[2][0] + sred[2][1]);
        __threadfence();
        unsigned old = atomicAdd(&g_fin, 1u);
        if (old == 15u) {
            __threadfence();
            double a = g_accKL, b = g_accT0, c = g_accL;
            double d_skl = a / (double)B_SZ * 0.5;
            double t0m   = b / (double)B_SZ;
            double meanL = c / (double)B_SZ;
            double lower = t0m - (meanL - log((double)B_SZ));
            out[0] = (float)(d_skl - lower);
        }
    }
}

// ---------------------------------------------------------------------------
// Launch DAG: stream0: reset, k1_q0..q3 (events after each).
// comp stream: per q — wait ev[q], k2_q, k3_shell_q.  Join back to stream0.
// ---------------------------------------------------------------------------
extern "C" void kernel_launch(void* const* d_in, const int* in_sizes, int n_in,
                              void* d_out, int out_size)
{
    const float* zl    = (const float*)d_in[0];
    const float* zv    = (const float*)d_in[1];
    const float* fclw  = (const float*)d_in[2];
    const float* fclb  = (const float*)d_in[3];
    const float* fcvw  = (const float*)d_in[4];
    const float* fcvb  = (const float*)d_in[5];
    const float* W1    = (const float*)d_in[6];
    const float* b1    = (const float*)d_in[7];
    const float* W2    = (const float*)d_in[8];
    const float* b2    = (const float*)d_in[9];
    const float* eps1  = (const float*)d_in[10];
    const float* eps2  = (const float*)d_in[11];
    float* out = (float*)d_out;

    static cudaStream_t s_comp = nullptr;
    static cudaEvent_t ev[5];
    if (!s_comp) {
        cudaStreamCreateWithFlags(&s_comp, cudaStreamNonBlocking);
        for (int i = 0; i < 5; ++i)
            cudaEventCreateWithFlags(&ev[i], cudaEventDisableTiming);
    }

    k_reset<<<1, 1>>>();
    for (int q = 0; q < 4; ++q) {
        k1_fuse<<<256, 192>>>(zl, zv, fclw, fclb, fcvw, fcvb, eps1, eps2,
                              q * 256);
        cudaEventRecord(ev[q], 0);
    }
    for (int q = 0; q < 4; ++q) {
        cudaStreamWaitEvent(s_comp, ev[q], 0);
        k2_gemm<<<dim3(4, 5, 2), 256, 0, s_comp>>>(W1, b1, q);
        k3_shell<<<32 * q + 16, 256, 0, s_comp>>>(W2, b2, out, q);
    }
    cudaEventRecord(ev[4], s_comp);
    cudaStreamWaitEvent(0, ev[4], 0);
}